// round 8
// baseline (speedup 1.0000x reference)
#include <cuda_runtime.h>

#define BB 4096
#define TT 365
#define HH 64
#define G4 256
#define HORIZON 7
#define ROWS 32
#define NCTA (BB / ROWS)      // 128
#define NTHREADS 512
#define PWK 256               // floats per k-slice: [unit0:i,f,g,o][unit1:...]...

// ---- shared memory layout (float offsets) ----
#define OFF_W0   0
#define OFF_W1   (OFF_W0 + 64 * PWK)        // 16384
#define OFF_H0A  (OFF_W1 + 128 * PWK)       // 49152
#define OFF_H0B  (OFF_H0A + 64 * ROWS)
#define OFF_H1A  (OFF_H0B + 64 * ROWS)
#define OFF_H1B  (OFF_H1A + 64 * ROWS)
#define OFF_PP   (OFF_H1B + 64 * ROWS)      // 16 warps x 32 rows
#define SMEM_FLOATS (OFF_PP + 16 * ROWS)    // 57856
#define SMEM_BYTES  (SMEM_FLOATS * 4)       // 231424 B <= 232448 cap

typedef unsigned long long ull;

// ---- packed f32x2 (Blackwell FFMA2 via PTX; ptxas won't auto-fuse) ----
__device__ __forceinline__ void fma2(ull &acc, ull a, ull b) {
    asm("fma.rn.f32x2 %0, %1, %2, %0;" : "+l"(acc) : "l"(a), "l"(b));
}
__device__ __forceinline__ ull pack2(float v) {
    ull r;
    asm("mov.b64 %0, {%1, %1};" : "=l"(r) : "r"(__float_as_uint(v)));
    return r;
}
__device__ __forceinline__ ull pack2d(float lo, float hi) {
    ull r;
    asm("mov.b64 %0, {%1, %2};" : "=l"(r) : "r"(__float_as_uint(lo)), "r"(__float_as_uint(hi)));
    return r;
}
__device__ __forceinline__ float2 unpack2(ull v) {
    unsigned int lo, hi;
    asm("mov.b64 {%0, %1}, %2;" : "=r"(lo), "=r"(hi) : "l"(v));
    return make_float2(__uint_as_float(lo), __uint_as_float(hi));
}

// ---- nonlinearities (MUFU ex2 + rcp, ~2 ulp) ----
__device__ __forceinline__ float sigm(float v) {
    return __fdividef(1.f, 1.f + __expf(-v));
}
__device__ __forceinline__ float tanh_(float v) {
    float a = fabsf(v);
    float e = __expf(-2.f * a);
    float r = __fdividef(1.f - e, 1.f + e);
    return copysignf(r, v);
}

// Thread tile: 4 batch rows (4rq..4rq+3) x 1 hidden unit (uc), all 4 gates.
// acc[j][0] = (gate_i, gate_f), acc[j][1] = (gate_g, gate_o) for row 4rq+j.

// gates += h @ W.  W interleaved [64 k][64 unit][4 gate]: one LDS.128 gives both
// gate-pair ulls pre-packed. h: [64 unit][32 row]: one LDS.128 gives 4 rows.
__device__ __forceinline__ void gemm64(ull acc[4][2], const float* __restrict__ wx,
                                       const float* __restrict__ hb, int rq, int uc) {
    const ulonglong2* wp = reinterpret_cast<const ulonglong2*>(wx) + uc;  // stride 64/k
    const float4* hp = reinterpret_cast<const float4*>(hb) + rq;          // stride 8/k
    #pragma unroll 8
    for (int k = 0; k < 64; ++k) {
        ulonglong2 w = wp[k * 64];      // w.x=(Wi,Wf)  w.y=(Wg,Wo)
        float4 hv = hp[k * 8];
        ull h0 = pack2(hv.x), h1 = pack2(hv.y), h2 = pack2(hv.z), h3 = pack2(hv.w);
        fma2(acc[0][0], w.x, h0); fma2(acc[0][1], w.y, h0);
        fma2(acc[1][0], w.x, h1); fma2(acc[1][1], w.y, h1);
        fma2(acc[2][0], w.x, h2); fma2(acc[2][1], w.y, h2);
        fma2(acc[3][0], w.x, h3); fma2(acc[3][1], w.y, h3);
    }
}

__device__ __forceinline__ void cell(ull acc[4][2], float c[4], float h[4]) {
    #pragma unroll
    for (int j = 0; j < 4; ++j) {
        float2 sif = unpack2(acc[j][0]);   // (i, f)
        float2 sgo = unpack2(acc[j][1]);   // (g, o)
        float cn = sigm(sif.y) * c[j] + sigm(sif.x) * tanh_(sgo.x);
        c[j] = cn;
        h[j] = sigm(sgo.y) * tanh_(cn);
    }
}

// Load big weights into SMEM, interleaved: WX[k*256 + u*4 + g] = W[g*64+u][k]
__device__ void load_weights(float* sm, const float* __restrict__ whh0,
                             const float* __restrict__ wih1, const float* __restrict__ whh1) {
    float* W0X = sm + OFF_W0;
    float* W1X = sm + OFF_W1;
    int tid = threadIdx.x;
    for (int e = tid; e < G4 * HH; e += NTHREADS) {
        int col = e >> 6;                 // 0..255 = g*64 + u
        int k = e & 63;
        int d = k * PWK + (col & 63) * 4 + (col >> 6);
        W0X[d] = whh0[e];
        W1X[d] = wih1[e];
        W1X[64 * PWK + d] = whh1[e];
    }
}

__global__ void __launch_bounds__(NTHREADS, 1)
lstm_kernel(const float* __restrict__ x,
            const float* __restrict__ eWih0, const float* __restrict__ eWhh0,
            const float* __restrict__ eb0,
            const float* __restrict__ eWih1, const float* __restrict__ eWhh1,
            const float* __restrict__ eb1,
            const float* __restrict__ dWih0, const float* __restrict__ dWhh0,
            const float* __restrict__ db0,
            const float* __restrict__ dWih1, const float* __restrict__ dWhh1,
            const float* __restrict__ db1,
            const float* __restrict__ fcW, const float* __restrict__ fcb,
            float* __restrict__ out) {
    extern __shared__ float sm[];
    const int tid = threadIdx.x;
    const int rq = tid & 7;         // rows 4rq..4rq+3
    const int uc = tid >> 3;        // 0..63: hidden unit
    const int wid = tid >> 5;       // warp id 0..15
    const int row0 = blockIdx.x * ROWS + 4 * rq;

    float* H0buf[2] = { sm + OFF_H0A, sm + OFF_H0B };
    float* H1buf[2] = { sm + OFF_H1A, sm + OFF_H1B };

    // ---------- encoder weights (SMEM) + per-thread constants (regs) ----------
    load_weights(sm, eWhh0, eWih1, eWhh1);
    for (int e = tid; e < 4 * 64 * ROWS; e += NTHREADS) sm[OFF_H0A + e] = 0.f;

    ull b0if = pack2d(eb0[uc], eb0[64 + uc]);
    ull b0go = pack2d(eb0[128 + uc], eb0[192 + uc]);
    ull b1if = pack2d(eb1[uc], eb1[64 + uc]);
    ull b1go = pack2d(eb1[128 + uc], eb1[192 + uc]);
    ull wiif = pack2d(eWih0[uc], eWih0[64 + uc]);
    ull wigo = pack2d(eWih0[128 + uc], eWih0[192 + uc]);
    __syncthreads();

    float c0[4] = {0.f, 0.f, 0.f, 0.f};
    float c1[4] = {0.f, 0.f, 0.f, 0.f};

    const float* xr = x + row0 * TT;
    float xv[4];
    #pragma unroll
    for (int j = 0; j < 4; ++j) xv[j] = xr[j * TT];

    // ---------- encoder: 365 steps, ONE barrier per step ----------
    for (int t = 0; t < TT; ++t) {
        float xn[4];
        #pragma unroll
        for (int j = 0; j < 4; ++j)
            xn[j] = (t + 1 < TT) ? xr[j * TT + t + 1] : 0.f;   // prefetch hides L2

        float* H0r = H0buf[t & 1];
        float* H0w = H0buf[(t + 1) & 1];
        float* H1r = H1buf[t & 1];
        float* H1w = H1buf[(t + 1) & 1];

        // layer 0: gates = b0 + x_t*Wih0 + h0 @ Whh0^T
        ull acc[4][2];
        #pragma unroll
        for (int j = 0; j < 4; ++j) {
            acc[j][0] = b0if; acc[j][1] = b0go;
            ull xx = pack2(xv[j]);
            fma2(acc[j][0], wiif, xx);
            fma2(acc[j][1], wigo, xx);
        }
        gemm64(acc, sm + OFF_W0, H0r, rq, uc);
        float h0[4];
        cell(acc, c0, h0);
        *reinterpret_cast<float4*>(H0w + uc * ROWS + 4 * rq) =
            make_float4(h0[0], h0[1], h0[2], h0[3]);
        __syncthreads();   // h0 visible; prev-step H1 stores visible; WAR covered

        // layer 1: gates = b1 + h0 @ Wih1^T + h1 @ Whh1^T
        #pragma unroll
        for (int j = 0; j < 4; ++j) { acc[j][0] = b1if; acc[j][1] = b1go; }
        gemm64(acc, sm + OFF_W1, H0w, rq, uc);
        gemm64(acc, sm + OFF_W1 + 64 * PWK, H1r, rq, uc);
        float h1[4];
        cell(acc, c1, h1);
        *reinterpret_cast<float4*>(H1w + uc * ROWS + 4 * rq) =
            make_float4(h1[0], h1[1], h1[2], h1[3]);
        // no second barrier: next step's barrier covers visibility + WAR

        #pragma unroll
        for (int j = 0; j < 4; ++j) xv[j] = xn[j];
    }
    __syncthreads();

    // ---------- decoder weights ----------
    load_weights(sm, dWhh0, dWih1, dWhh1);
    b0if = pack2d(db0[uc], db0[64 + uc]);
    b0go = pack2d(db0[128 + uc], db0[192 + uc]);
    b1if = pack2d(db1[uc], db1[64 + uc]);
    b1go = pack2d(db1[128 + uc], db1[192 + uc]);
    wiif = pack2d(dWih0[uc], dWih0[64 + uc]);
    wigo = pack2d(dWih0[128 + uc], dWih0[192 + uc]);
    const float fcw = fcW[uc];
    const float fcbv = fcb[0];
    __syncthreads();

    // ---------- decoder: 7 autoregressive steps ----------
    float din[4] = {0.f, 0.f, 0.f, 0.f};
    for (int s = 0; s < HORIZON; ++s) {
        int t = TT + s;
        float* H0r = H0buf[t & 1];
        float* H0w = H0buf[(t + 1) & 1];
        float* H1r = H1buf[t & 1];
        float* H1w = H1buf[(t + 1) & 1];

        ull acc[4][2];
        #pragma unroll
        for (int j = 0; j < 4; ++j) {
            acc[j][0] = b0if; acc[j][1] = b0go;
            ull xx = pack2(din[j]);
            fma2(acc[j][0], wiif, xx);
            fma2(acc[j][1], wigo, xx);
        }
        gemm64(acc, sm + OFF_W0, H0r, rq, uc);
        float h0[4];
        cell(acc, c0, h0);
        *reinterpret_cast<float4*>(H0w + uc * ROWS + 4 * rq) =
            make_float4(h0[0], h0[1], h0[2], h0[3]);
        __syncthreads();

        #pragma unroll
        for (int j = 0; j < 4; ++j) { acc[j][0] = b1if; acc[j][1] = b1go; }
        gemm64(acc, sm + OFF_W1, H0w, rq, uc);
        gemm64(acc, sm + OFF_W1 + 64 * PWK, H1r, rq, uc);
        float h1[4];
        cell(acc, c1, h1);
        *reinterpret_cast<float4*>(H1w + uc * ROWS + 4 * rq) =
            make_float4(h1[0], h1[1], h1[2], h1[3]);

        // FC: part over this thread's unit, reduce 4 units within warp (lanes +-8,16)
        float part[4];
        #pragma unroll
        for (int j = 0; j < 4; ++j) {
            float v = h1[j] * fcw;
            v += __shfl_xor_sync(0xFFFFFFFFu, v, 8);
            v += __shfl_xor_sync(0xFFFFFFFFu, v, 16);
            part[j] = v;
        }
        if ((tid & 31) < 8)
            *reinterpret_cast<float4*>(sm + OFF_PP + wid * ROWS + 4 * rq) =
                make_float4(part[0], part[1], part[2], part[3]);
        __syncthreads();

        if (tid < ROWS) {
            float sum = fcbv;
            #pragma unroll
            for (int w = 0; w < 16; ++w) sum += sm[OFF_PP + w * ROWS + tid];
            out[(blockIdx.x * ROWS + tid) * HORIZON + s] = sum;
            sm[OFF_PP + tid] = sum;    // reuse PP[0..31] as feedback slot
        }
        __syncthreads();
        float4 dv = *reinterpret_cast<const float4*>(sm + OFF_PP + 4 * rq);
        din[0] = dv.x; din[1] = dv.y; din[2] = dv.z; din[3] = dv.w;
    }
}

extern "C" void kernel_launch(void* const* d_in, const int* in_sizes, int n_in,
                              void* d_out, int out_size) {
    cudaFuncSetAttribute(lstm_kernel, cudaFuncAttributeMaxDynamicSharedMemorySize, SMEM_BYTES);
    lstm_kernel<<<NCTA, NTHREADS, SMEM_BYTES>>>(
        (const float*)d_in[0],                                   // x
        (const float*)d_in[1], (const float*)d_in[2], (const float*)d_in[3],   // enc L0
        (const float*)d_in[4], (const float*)d_in[5], (const float*)d_in[6],   // enc L1
        (const float*)d_in[7], (const float*)d_in[8], (const float*)d_in[9],   // dec L0
        (const float*)d_in[10], (const float*)d_in[11], (const float*)d_in[12],// dec L1
        (const float*)d_in[13], (const float*)d_in[14],          // fc
        (float*)d_out);
}

// round 9
// speedup vs baseline: 2.0825x; 2.0825x over previous
#include <cuda_runtime.h>
#include <cuda_bf16.h>

#define BB 4096
#define TT 365
#define HORIZON 7
#define ROWS 32
#define NCTA (BB / ROWS)     // 128
#define NTH 512

// ---- SMEM byte offsets (all arrays 128B-row pitch, SW128 swizzled) ----
#define OFF_W0H   0u          // Whh0 hi   [256 cols][64 k] bf16
#define OFF_W0L   32768u      // Whh0 lo
#define OFF_W1AH  65536u      // Wih1 hi   (L1, k from h0)
#define OFF_W1AL  98304u
#define OFF_W1BH  131072u     // Whh1 hi   (L1, k from h1)
#define OFF_W1BL  163840u
#define OFF_AH0   196608u     // h0[buf 2][split 2]: 32 rows x 64 units bf16 = 4096B each
#define OFF_AH1   212992u     // h1[buf 2][split 2]
#define SMEM_BYTES 229376u

// decoder FC scratch (per-CTA slices of device globals; no allocation)
__device__ float g_pp[NCTA][8][32];
__device__ float g_fb[NCTA][32];

__device__ __forceinline__ unsigned swz(unsigned o) { return o ^ ((o >> 3) & 0x70u); }

__device__ __forceinline__ void ldsm4(unsigned &r0, unsigned &r1, unsigned &r2, unsigned &r3,
                                      unsigned a) {
    asm volatile("ldmatrix.sync.aligned.m8n8.x4.shared.b16 {%0,%1,%2,%3}, [%4];"
                 : "=r"(r0), "=r"(r1), "=r"(r2), "=r"(r3) : "r"(a));
}

__device__ __forceinline__ void mma16816(float d[4], unsigned a0, unsigned a1, unsigned a2,
                                         unsigned a3, unsigned b0, unsigned b1) {
    asm volatile("mma.sync.aligned.m16n8k16.row.col.f32.bf16.bf16.f32 "
                 "{%0,%1,%2,%3},{%4,%5,%6,%7},{%8,%9},{%0,%1,%2,%3};"
                 : "+f"(d[0]), "+f"(d[1]), "+f"(d[2]), "+f"(d[3])
                 : "r"(a0), "r"(a1), "r"(a2), "r"(a3), "r"(b0), "r"(b1));
}

__device__ __forceinline__ float sigm(float v) {
    return __fdividef(1.f, 1.f + __expf(-v));
}
__device__ __forceinline__ float tanh_(float v) {
    float a = fabsf(v);
    float e = __expf(-2.f * a);
    float r = __fdividef(1.f - e, 1.f + e);
    return copysignf(r, v);
}

// gates[4 ntiles] += A(32x64 split) @ W(64x256 split), 3-product bf16 split.
__device__ __forceinline__ void gemm16(float acc[4][4], unsigned sb,
                                       unsigned aH, unsigned aL,
                                       unsigned wH, unsigned wL,
                                       unsigned raOff, unsigned cbOff) {
    #pragma unroll
    for (int ks = 0; ks < 4; ++ks) {
        unsigned ah0, ah1, ah2, ah3, al0, al1, al2, al3;
        ldsm4(ah0, ah1, ah2, ah3, sb + aH + swz(raOff + ks * 32));
        ldsm4(al0, al1, al2, al3, sb + aL + swz(raOff + ks * 32));
        #pragma unroll
        for (int tp = 0; tp < 2; ++tp) {
            unsigned bh0, bh1, bh2, bh3, bl0, bl1, bl2, bl3;
            ldsm4(bh0, bh1, bh2, bh3, sb + wH + swz(cbOff + tp * 2048 + ks * 32));
            ldsm4(bl0, bl1, bl2, bl3, sb + wL + swz(cbOff + tp * 2048 + ks * 32));
            mma16816(acc[2 * tp],     ah0, ah1, ah2, ah3, bh0, bh1);
            mma16816(acc[2 * tp],     ah0, ah1, ah2, ah3, bl0, bl1);
            mma16816(acc[2 * tp],     al0, al1, al2, al3, bh0, bh1);
            mma16816(acc[2 * tp + 1], ah0, ah1, ah2, ah3, bh2, bh3);
            mma16816(acc[2 * tp + 1], ah0, ah1, ah2, ah3, bl2, bl3);
            mma16816(acc[2 * tp + 1], al0, al1, al2, al3, bh2, bh3);
        }
    }
}

// LSTM cell over this lane's 4 tiles x 2 rows. Lane pair (l, l^1) holds
// (i,f)/(g,o) of one unit; shfl_xor(1) completes the gate set (both lanes
// compute identical results -> deterministic).
__device__ __forceinline__ void cellq(float acc[4][4], float *cst, float hv[4][2], int ifh) {
    #pragma unroll
    for (int t = 0; t < 4; ++t) {
        float e0 = __shfl_xor_sync(0xFFFFFFFFu, acc[t][0], 1);
        float e1 = __shfl_xor_sync(0xFFFFFFFFu, acc[t][1], 1);
        float e2 = __shfl_xor_sync(0xFFFFFFFFu, acc[t][2], 1);
        float e3 = __shfl_xor_sync(0xFFFFFFFFu, acc[t][3], 1);
        float gi = ifh ? acc[t][0] : e0;
        float gf = ifh ? acc[t][1] : e1;
        float gg = ifh ? e0 : acc[t][0];
        float go = ifh ? e1 : acc[t][1];
        float cn = sigm(gf) * cst[2 * t] + sigm(gi) * tanh_(gg);
        cst[2 * t] = cn;
        hv[t][0] = sigm(go) * tanh_(cn);
        gi = ifh ? acc[t][2] : e2;
        gf = ifh ? acc[t][3] : e3;
        gg = ifh ? e2 : acc[t][2];
        go = ifh ? e3 : acc[t][3];
        cn = sigm(gf) * cst[2 * t + 1] + sigm(gi) * tanh_(gg);
        cst[2 * t + 1] = cn;
        hv[t][1] = sigm(go) * tanh_(cn);
    }
}

// bf16 hi/lo split writeback of h (writer lanes only: one lane per pair).
__device__ __forceinline__ void storehq(char *smp, unsigned offH, unsigned offL,
                                        const float hv[4][2], int nb, int ug,
                                        int rA, int rB, int writer) {
    if (!writer) return;
    #pragma unroll
    for (int t = 0; t < 4; ++t) {
        int u = 2 * (nb + t) + ug;
        unsigned oA = swz((unsigned)(rA * 128 + u * 2));
        unsigned oB = swz((unsigned)(rB * 128 + u * 2));
        __nv_bfloat16 hA = __float2bfloat16(hv[t][0]);
        __nv_bfloat16 lA = __float2bfloat16(hv[t][0] - __bfloat162float(hA));
        __nv_bfloat16 hB = __float2bfloat16(hv[t][1]);
        __nv_bfloat16 lB = __float2bfloat16(hv[t][1] - __bfloat162float(hB));
        *(__nv_bfloat16 *)(smp + offH + oA) = hA;
        *(__nv_bfloat16 *)(smp + offL + oA) = lA;
        *(__nv_bfloat16 *)(smp + offH + oB) = hB;
        *(__nv_bfloat16 *)(smp + offL + oB) = lB;
    }
}

// Split-store raw fp32 weights [256 gate-rows][64 k] into gate-interleaved
// swizzled bf16 hi/lo: col c = u*4 + g, addr = swz(c*128 + k*2).
__device__ void store_w(char *smp, unsigned offH, unsigned offL, const float *__restrict__ raw) {
    for (int e = threadIdx.x; e < 256 * 64; e += NTH) {
        int R = e >> 6, k = e & 63;
        int c = (R & 63) * 4 + (R >> 6);
        float w = raw[e];
        __nv_bfloat16 hi = __float2bfloat16(w);
        __nv_bfloat16 lo = __float2bfloat16(w - __bfloat162float(hi));
        unsigned o = swz((unsigned)(c * 128 + k * 2));
        *(__nv_bfloat16 *)(smp + offH + o) = hi;
        *(__nv_bfloat16 *)(smp + offL + o) = lo;
    }
}

__global__ void __launch_bounds__(NTH, 1)
lstm_kernel(const float *__restrict__ x,
            const float *__restrict__ eWih0, const float *__restrict__ eWhh0,
            const float *__restrict__ eb0,
            const float *__restrict__ eWih1, const float *__restrict__ eWhh1,
            const float *__restrict__ eb1,
            const float *__restrict__ dWih0, const float *__restrict__ dWhh0,
            const float *__restrict__ db0,
            const float *__restrict__ dWih1, const float *__restrict__ dWhh1,
            const float *__restrict__ db1,
            const float *__restrict__ fcW, const float *__restrict__ fcb,
            float *__restrict__ out) {
    extern __shared__ char smem[];
    unsigned sb = (unsigned)__cvta_generic_to_shared(smem);

    const int tid = threadIdx.x;
    const int lane = tid & 31;
    const int wid = tid >> 5;
    const int mw = wid & 1;              // m-tile: rows 16mw..16mw+15
    const int nb = (wid >> 1) * 4;       // 4 n-tiles: cols 8nb..8nb+31
    const int blk = blockIdx.x;

    const int ifh = !(lane & 1);         // lane holds (i,f); partner holds (g,o)
    const int ug = (lane >> 1) & 1;      // unit-in-tile
    const int rA = mw * 16 + (lane >> 2);
    const int rB = rA + 8;

    // ldmatrix per-lane address bases (SW128-swizzled arrays, 128B row pitch)
    const unsigned raOff = (unsigned)((mw * 16 + (lane & 7) + (lane & 8)) * 128
                                      + ((lane >> 4) & 1) * 16);
    const unsigned cbOff = (unsigned)((8 * nb + (lane & 7) + 8 * ((lane >> 4) & 1)) * 128
                                      + ((lane >> 3) & 1) * 16);

    // tile gate columns for this lane (interleaved layout: c = u*4 + g)
    int cI[4][2];
    #pragma unroll
    for (int t = 0; t < 4; ++t) {
        int c0 = 8 * (nb + t) + ((lane & 3) << 1);
        cI[t][0] = (c0 & 3) * 64 + (c0 >> 2);          // raw gate-row index
        cI[t][1] = ((c0 + 1) & 3) * 64 + ((c0 + 1) >> 2);
    }

    // ---------- encoder weights ----------
    store_w(smem, OFF_W0H, OFF_W0L, eWhh0);
    store_w(smem, OFF_W1AH, OFF_W1AL, eWih1);
    store_w(smem, OFF_W1BH, OFF_W1BL, eWhh1);
    for (int i = tid; i < 8192; i += NTH) ((float *)(smem + OFF_AH0))[i] = 0.f;  // h bufs

    float b0c[4][2], b1c[4][2], wic[4][2];
    #pragma unroll
    for (int t = 0; t < 4; ++t) {
        b0c[t][0] = eb0[cI[t][0]]; b0c[t][1] = eb0[cI[t][1]];
        b1c[t][0] = eb1[cI[t][0]]; b1c[t][1] = eb1[cI[t][1]];
        wic[t][0] = eWih0[cI[t][0]]; wic[t][1] = eWih0[cI[t][1]];
    }
    __syncthreads();

    float c0s[8], c1s[8];
    #pragma unroll
    for (int i = 0; i < 8; ++i) { c0s[i] = 0.f; c1s[i] = 0.f; }

    const float *xrA = x + (blk * 32 + rA) * TT;
    const float *xrB = x + (blk * 32 + rB) * TT;
    float xA = xrA[0], xB = xrB[0];

    // ---------- encoder: 365 steps, 1 barrier/step ----------
    for (int t = 0; t < TT; ++t) {
        float xnA = (t + 1 < TT) ? xrA[t + 1] : 0.f;
        float xnB = (t + 1 < TT) ? xrB[t + 1] : 0.f;
        unsigned p = (unsigned)(t & 1);

        unsigned h0r = OFF_AH0 + p * 8192;            // [split 0 | split 1 (+4096)]
        unsigned h0w = OFF_AH0 + (p ^ 1) * 8192;
        unsigned h1r = OFF_AH1 + p * 8192;
        unsigned h1w = OFF_AH1 + (p ^ 1) * 8192;

        // layer 0: acc = b0 + x*wi ; += h0_prev @ Whh0
        float acc[4][4];
        #pragma unroll
        for (int tt = 0; tt < 4; ++tt) {
            acc[tt][0] = fmaf(xA, wic[tt][0], b0c[tt][0]);
            acc[tt][1] = fmaf(xA, wic[tt][1], b0c[tt][1]);
            acc[tt][2] = fmaf(xB, wic[tt][0], b0c[tt][0]);
            acc[tt][3] = fmaf(xB, wic[tt][1], b0c[tt][1]);
        }
        gemm16(acc, sb, h0r, h0r + 4096, OFF_W0H, OFF_W0L, raOff, cbOff);
        float hv[4][2];
        cellq(acc, c0s, hv, ifh);
        storehq(smem, h0w, h0w + 4096, hv, nb, ug, rA, rB, ifh);
        __syncthreads();

        // layer 1: acc = b1 ; += h0_cur @ Wih1 ; += h1_prev @ Whh1
        #pragma unroll
        for (int tt = 0; tt < 4; ++tt) {
            acc[tt][0] = b1c[tt][0]; acc[tt][1] = b1c[tt][1];
            acc[tt][2] = b1c[tt][0]; acc[tt][3] = b1c[tt][1];
        }
        gemm16(acc, sb, h0w, h0w + 4096, OFF_W1AH, OFF_W1AL, raOff, cbOff);
        gemm16(acc, sb, h1r, h1r + 4096, OFF_W1BH, OFF_W1BL, raOff, cbOff);
        cellq(acc, c1s, hv, ifh);
        storehq(smem, h1w, h1w + 4096, hv, nb, ug, rA, rB, ifh);
        // no 2nd barrier: next step's barrier covers h1 visibility + WAR

        xA = xnA; xB = xnB;
    }
    __syncthreads();     // all encoder-weight reads done

    // ---------- decoder weights ----------
    store_w(smem, OFF_W0H, OFF_W0L, dWhh0);
    store_w(smem, OFF_W1AH, OFF_W1AL, dWih1);
    store_w(smem, OFF_W1BH, OFF_W1BL, dWhh1);
    float fcw4[4];
    #pragma unroll
    for (int t = 0; t < 4; ++t) {
        b0c[t][0] = db0[cI[t][0]]; b0c[t][1] = db0[cI[t][1]];
        b1c[t][0] = db1[cI[t][0]]; b1c[t][1] = db1[cI[t][1]];
        wic[t][0] = dWih0[cI[t][0]]; wic[t][1] = dWih0[cI[t][1]];
        fcw4[t] = fcW[2 * (nb + t) + ug];
    }
    const float fcbv = fcb[0];
    __syncthreads();

    // ---------- decoder: 7 autoregressive steps ----------
    xA = 0.f; xB = 0.f;
    for (int s = 0; s < HORIZON; ++s) {
        unsigned p = (unsigned)((TT + s) & 1);
        unsigned h0r = OFF_AH0 + p * 8192;
        unsigned h0w = OFF_AH0 + (p ^ 1) * 8192;
        unsigned h1r = OFF_AH1 + p * 8192;
        unsigned h1w = OFF_AH1 + (p ^ 1) * 8192;

        float acc[4][4];
        #pragma unroll
        for (int tt = 0; tt < 4; ++tt) {
            acc[tt][0] = fmaf(xA, wic[tt][0], b0c[tt][0]);
            acc[tt][1] = fmaf(xA, wic[tt][1], b0c[tt][1]);
            acc[tt][2] = fmaf(xB, wic[tt][0], b0c[tt][0]);
            acc[tt][3] = fmaf(xB, wic[tt][1], b0c[tt][1]);
        }
        gemm16(acc, sb, h0r, h0r + 4096, OFF_W0H, OFF_W0L, raOff, cbOff);
        float hv[4][2];
        cellq(acc, c0s, hv, ifh);
        storehq(smem, h0w, h0w + 4096, hv, nb, ug, rA, rB, ifh);
        __syncthreads();

        #pragma unroll
        for (int tt = 0; tt < 4; ++tt) {
            acc[tt][0] = b1c[tt][0]; acc[tt][1] = b1c[tt][1];
            acc[tt][2] = b1c[tt][0]; acc[tt][3] = b1c[tt][1];
        }
        gemm16(acc, sb, h0w, h0w + 4096, OFF_W1AH, OFF_W1AL, raOff, cbOff);
        gemm16(acc, sb, h1r, h1r + 4096, OFF_W1BH, OFF_W1BL, raOff, cbOff);
        cellq(acc, c1s, hv, ifh);
        storehq(smem, h1w, h1w + 4096, hv, nb, ug, rA, rB, ifh);

        // FC: per-lane partial over its 4 units (writer lanes), pair-sum, store
        float v0 = 0.f, v1 = 0.f;
        if (ifh) {
            #pragma unroll
            for (int tt = 0; tt < 4; ++tt) {
                v0 += hv[tt][0] * fcw4[tt];
                v1 += hv[tt][1] * fcw4[tt];
            }
        }
        v0 += __shfl_xor_sync(0xFFFFFFFFu, v0, 2);
        v1 += __shfl_xor_sync(0xFFFFFFFFu, v1, 2);
        if ((lane & 3) == 0) {
            g_pp[blk][wid >> 1][rA] = v0;
            g_pp[blk][wid >> 1][rB] = v1;
        }
        __syncthreads();
        if (tid < 32) {
            float sum = fcbv;
            #pragma unroll
            for (int j = 0; j < 8; ++j) sum += g_pp[blk][j][tid];
            out[(blk * 32 + tid) * HORIZON + s] = sum;
            g_fb[blk][tid] = sum;
        }
        __syncthreads();
        xA = g_fb[blk][rA];
        xB = g_fb[blk][rB];
    }
}

extern "C" void kernel_launch(void *const *d_in, const int *in_sizes, int n_in,
                              void *d_out, int out_size) {
    cudaFuncSetAttribute(lstm_kernel, cudaFuncAttributeMaxDynamicSharedMemorySize, SMEM_BYTES);
    lstm_kernel<<<NCTA, NTH, SMEM_BYTES>>>(
        (const float *)d_in[0],
        (const float *)d_in[1], (const float *)d_in[2], (const float *)d_in[3],
        (const float *)d_in[4], (const float *)d_in[5], (const float *)d_in[6],
        (const float *)d_in[7], (const float *)d_in[8], (const float *)d_in[9],
        (const float *)d_in[10], (const float *)d_in[11], (const float *)d_in[12],
        (const float *)d_in[13], (const float *)d_in[14],
        (float *)d_out);
}